// round 11
// baseline (speedup 1.0000x reference)
#include <cuda_runtime.h>
#include <cuda_bf16.h>
#include <cstdint>

typedef uint32_t u32;

// ---- bf16 helpers ----
__device__ __forceinline__ u32 bf2(float lo, float hi) {   // lo -> low 16 bits
    u32 r; asm("cvt.rn.bf16x2.f32 %0, %1, %2;" : "=r"(r) : "f"(hi), "f"(lo)); return r;
}
__device__ __forceinline__ float lo_f32(u32 p) { return __uint_as_float(p << 16); }
__device__ __forceinline__ float hi_f32(u32 p) { return __uint_as_float(p & 0xFFFF0000u); }
__device__ __forceinline__ float rbf(float v) {
    return __bfloat162float(__float2bfloat16(v));
}

// ---- f32 tanh (MUFU) ----
__device__ __forceinline__ float tanha(float x) {
    float r; asm("tanh.approx.f32 %0, %1;" : "=f"(r) : "f"(x)); return r;
}

// D += A * B  (m16n8k16, bf16 in, f32 accum); only D rows 0-7 (d[0],d[1])
// carry live data in this kernel, rows 8-15 are ignored.
__device__ __forceinline__ void mma16816(float* d, u32 a0, u32 a1, u32 a2, u32 a3,
                                         u32 b0, u32 b1) {
    asm("mma.sync.aligned.m16n8k16.row.col.f32.bf16.bf16.f32 "
        "{%0,%1,%2,%3}, {%4,%5,%6,%7}, {%8,%9}, {%0,%1,%2,%3};"
        : "+f"(d[0]), "+f"(d[1]), "+f"(d[2]), "+f"(d[3])
        : "r"(a0), "r"(a1), "r"(a2), "r"(a3), "r"(b0), "r"(b1));
}

// Cell update, 2 cells, pure f32, algebra-trimmed:
//   gates i,f,o arrive prescaled by 0.5 (z/2); ti=tanh(z/2) => 2*sig(z)=ti+1.
//   c' = 0.5*((tf+1)c + (ti+1)g) = f*c + i*g
//   h~ = (to+1)*tanh(c') = 2h   (the 0.5 is folded into all h-consumers' W)
__device__ __forceinline__ void cell2(const float* gi, const float* gf,
                                      const float* gg, const float* gq,
                                      float* c, float* ht) {
#pragma unroll
    for (int j = 0; j < 2; j++) {
        float ti = tanha(gi[j]);
        float tf = tanha(gf[j]);
        float tG = tanha(gg[j]);
        float to = tanha(gq[j]);
        float A  = fmaf(tf, c[j], c[j]);     // 2*f*c
        float Bt = fmaf(ti, tG, tG);         // 2*i*g
        c[j] = 0.5f * (A + Bt);
        float T = tanha(c[j]);
        ht[j] = fmaf(to, T, T);              // 2h
    }
}

// One warp = 8 sequences (MMA rows 0-7; rows 8-15 zero/ignored). 128-thread
// blocks (4 warps) keep all 4 SMSPs fed; grid = B/32 = 1024 gives fine-grained
// blocks -> multi-wave work-stealing evens the SM load (the 512-block version
// left 68 SMs pacing the chip 16% slower in a single wave).
// Per step, per gate:
//  L0 (depth-2 chain on d0): d0 = bias + Wih*x (exact f32 FFMA);
//      MMA(d0,[h~hi|h~lo],[W0hi|W0hi]); MMA(d0,[h~hi|0],[W0lo|W0lo]).
//  L1: d1 = bias + MMA([h0hi|h1hi],[B1hi]); e1 = MMA([h0lo|h1lo],[B1hi])
//      + MMA([h0hi|h1hi],[B1lo]) chained; gate = d1+e1.  Full hi/lo product.
// Software pipeline: L0(t+1) issued before consuming L1(t).
// h~ = 2h recirculates; all W consuming h carry an extra 0.5.
__global__ void __launch_bounds__(128) lstm_mma6(
    const float* __restrict__ input,
    const float* __restrict__ w_ih0, const float* __restrict__ w_hh0,
    const float* __restrict__ b_ih0, const float* __restrict__ b_hh0,
    const float* __restrict__ w_ih1, const float* __restrict__ w_hh1,
    const float* __restrict__ b_ih1, const float* __restrict__ b_hh1,
    const float* __restrict__ w_mlp, const float* __restrict__ b_mlp,
    float* __restrict__ out, int B)
{
    const int T = 256;
    int lane = threadIdx.x & 31;
    int gid  = lane >> 2;          // 0..7 : seq row / B-frag n index
    int tg   = lane & 3;           // 0..3 : hidden-pair index
    int warp = (blockIdx.x * (blockDim.x >> 5)) + (threadIdx.x >> 5);
    int rA   = warp * 8 + gid;     // this thread-group's sequence
    int rAc  = (rA < B) ? rA : (B - 1);

    // ---- weights: bf16 hi+lo B frags (extra 0.5 for h~=2h), f32 x-w, biases ----
    u32 B0h[4], B0l[4], B1ah[4], B1bh[4], B1al[4], B1bl[4];
    float wi00[4], wi01[4], wi10[4], wi11[4];
    float be0[4], bo0[4], be1[4], bo1[4];
#pragma unroll
    for (int g = 0; g < 4; g++) {
        int wr = g * 8 + gid;
        float s  = (g == 2) ? 1.0f : 0.5f;   // sigmoid gate prescale
        float sh = s * 0.5f;                  // + h~=2h compensation
        float a0 = sh * w_hh0[wr * 8 + tg * 2], a1 = sh * w_hh0[wr * 8 + tg * 2 + 1];
        float u0 = sh * w_ih1[wr * 8 + tg * 2], u1 = sh * w_ih1[wr * 8 + tg * 2 + 1];
        float v0 = sh * w_hh1[wr * 8 + tg * 2], v1 = sh * w_hh1[wr * 8 + tg * 2 + 1];
        B0h[g]  = bf2(rbf(a0), rbf(a1));  B0l[g]  = bf2(a0 - rbf(a0), a1 - rbf(a1));
        B1ah[g] = bf2(rbf(u0), rbf(u1));  B1al[g] = bf2(u0 - rbf(u0), u1 - rbf(u1));
        B1bh[g] = bf2(rbf(v0), rbf(v1));  B1bl[g] = bf2(v0 - rbf(v0), v1 - rbf(v1));
        int cE = g * 8 + tg * 2;             // D cols: hid = tg*2, tg*2+1
        wi00[g] = s * w_ih0[cE * 2];         wi01[g] = s * w_ih0[cE * 2 + 1];
        wi10[g] = s * w_ih0[(cE + 1) * 2];   wi11[g] = s * w_ih0[(cE + 1) * 2 + 1];
        be0[g] = s * (b_ih0[cE] + b_hh0[cE]);
        bo0[g] = s * (b_ih0[cE + 1] + b_hh0[cE + 1]);
        be1[g] = s * (b_ih1[cE] + b_hh1[cE]);
        bo1[g] = s * (b_ih1[cE + 1] + b_hh1[cE + 1]);
    }

    // ---- state (2 cells per layer per thread) ----
    float c0[2] = {0.f, 0.f};
    float c1[2] = {0.f, 0.f};
    float h1t[2] = {0.f, 0.f};
    u32 h0hi = 0, h0lo = 0, h1hi = 0, h1lo = 0;

    const float2* xr = reinterpret_cast<const float2*>(input);

    // ---- prologue: L0(0) = bias + Wih*x(0); h0(-1)=0 so no MMA ----
    float d0[4][4];
    {
        float2 xA = __ldg(&xr[(size_t)rAc * T]);
#pragma unroll
        for (int g = 0; g < 4; g++) {
            d0[g][0] = fmaf(wi01[g], xA.y, fmaf(wi00[g], xA.x, be0[g]));
            d0[g][1] = fmaf(wi11[g], xA.y, fmaf(wi10[g], xA.x, bo0[g]));
            d0[g][2] = 0.f; d0[g][3] = 0.f;
        }
    }

    for (int t = 0; t < T; t++) {
        // ---- consume L0(t) -> h0(t) ----
        float gi[2] = {d0[0][0], d0[0][1]};
        float gf[2] = {d0[1][0], d0[1][1]};
        float gg[2] = {d0[2][0], d0[2][1]};
        float gq[2] = {d0[3][0], d0[3][1]};
        float h0t[2];
        cell2(gi, gf, gg, gq, c0, h0t);
        h0hi = bf2(h0t[0], h0t[1]);
        h0lo = bf2(h0t[0] - lo_f32(h0hi), h0t[1] - hi_f32(h0hi));

        // ---- issue L1(t): d1 main + e1 corrections (full hi/lo) ----
        float d1[4][4], e1[4][4];
#pragma unroll
        for (int g = 0; g < 4; g++) {
            d1[g][0] = be1[g]; d1[g][1] = bo1[g]; d1[g][2] = 0.f; d1[g][3] = 0.f;
            e1[g][0] = 0.f; e1[g][1] = 0.f; e1[g][2] = 0.f; e1[g][3] = 0.f;
            mma16816(d1[g], h0hi, 0u, h1hi, 0u, B1ah[g], B1bh[g]);
            mma16816(e1[g], h0lo, 0u, h1lo, 0u, B1ah[g], B1bh[g]);
            mma16816(e1[g], h0hi, 0u, h1hi, 0u, B1al[g], B1bl[g]);
        }

        // ---- issue L0(t+1): exact x/bias init + depth-2 chain (full W) ----
        {
            int tn = (t < T - 1) ? (t + 1) : t;
            float2 xA = __ldg(&xr[(size_t)rAc * T + tn]);
#pragma unroll
            for (int g = 0; g < 4; g++) {
                d0[g][0] = fmaf(wi01[g], xA.y, fmaf(wi00[g], xA.x, be0[g]));
                d0[g][1] = fmaf(wi11[g], xA.y, fmaf(wi10[g], xA.x, bo0[g]));
                d0[g][2] = 0.f; d0[g][3] = 0.f;
                mma16816(d0[g], h0hi, 0u, h0lo, 0u, B0h[g], B0h[g]);
                mma16816(d0[g], h0hi, 0u, 0u, 0u, B0l[g], B0l[g]);
            }
        }

        // ---- consume L1(t) -> h1(t) ----
#pragma unroll
        for (int j = 0; j < 2; j++) {
            gi[j] = d1[0][j] + e1[0][j];
            gf[j] = d1[1][j] + e1[1][j];
            gg[j] = d1[2][j] + e1[2][j];
            gq[j] = d1[3][j] + e1[3][j];
        }
        cell2(gi, gf, gg, gq, c1, h1t);
        h1hi = bf2(h1t[0], h1t[1]);
        h1lo = bf2(h1t[0] - lo_f32(h1hi), h1t[1] - hi_f32(h1hi));
    }

    // ================= MLP head (h~=2h -> 0.5*w_mlp) =================
    int hidE = tg * 2;
    float p0 = h1t[0] * (0.5f * w_mlp[hidE])     + h1t[1] * (0.5f * w_mlp[hidE + 1]);
    float p1 = h1t[0] * (0.5f * w_mlp[8 + hidE]) + h1t[1] * (0.5f * w_mlp[8 + hidE + 1]);
#pragma unroll
    for (int off = 1; off < 4; off <<= 1) {
        p0 += __shfl_xor_sync(0xffffffffu, p0, off);
        p1 += __shfl_xor_sync(0xffffffffu, p1, off);
    }
    if (tg == 0 && rA < B) {
        float2 o; o.x = p0 + b_mlp[0]; o.y = p1 + b_mlp[1];
        reinterpret_cast<float2*>(out)[rA] = o;
    }
}

extern "C" void kernel_launch(void* const* d_in, const int* in_sizes, int n_in,
                              void* d_out, int out_size) {
    const float* input = (const float*)d_in[0];
    const float* w_ih0 = (const float*)d_in[1];
    const float* w_hh0 = (const float*)d_in[2];
    const float* b_ih0 = (const float*)d_in[3];
    const float* b_hh0 = (const float*)d_in[4];
    const float* w_ih1 = (const float*)d_in[5];
    const float* w_hh1 = (const float*)d_in[6];
    const float* b_ih1 = (const float*)d_in[7];
    const float* b_hh1 = (const float*)d_in[8];
    const float* w_mlp = (const float*)d_in[9];
    const float* b_mlp = (const float*)d_in[10];

    const int T = 256, IN = 2;
    int B = in_sizes[0] / (T * IN);

    // 8 seqs/warp, 4 warps/block (128 threads) => 32 seqs/block
    int grid = (B + 31) / 32;
    lstm_mma6<<<grid, 128>>>(input, w_ih0, w_hh0, b_ih0, b_hh0,
                             w_ih1, w_hh1, b_ih1, b_hh1,
                             w_mlp, b_mlp, (float*)d_out, B);
}

// round 12
// speedup vs baseline: 1.1473x; 1.1473x over previous
#include <cuda_runtime.h>
#include <cuda_bf16.h>
#include <cstdint>

typedef uint32_t u32;

// ---- bf16 helpers ----
__device__ __forceinline__ u32 bf2(float lo, float hi) {   // lo -> low 16 bits
    u32 r; asm("cvt.rn.bf16x2.f32 %0, %1, %2;" : "=r"(r) : "f"(hi), "f"(lo)); return r;
}
__device__ __forceinline__ float lo_f32(u32 p) { return __uint_as_float(p << 16); }
__device__ __forceinline__ float hi_f32(u32 p) { return __uint_as_float(p & 0xFFFF0000u); }
__device__ __forceinline__ float rbf(float v) {
    return __bfloat162float(__float2bfloat16(v));
}

// ---- f32 tanh (MUFU) ----
__device__ __forceinline__ float tanha(float x) {
    float r; asm("tanh.approx.f32 %0, %1;" : "=f"(r) : "f"(x)); return r;
}

// D = A*B + C  (m16n8k16 bf16->f32), C = separate (persistent bias) registers
__device__ __forceinline__ void mma_c(float* d, u32 a0, u32 a1, u32 a2, u32 a3,
                                      u32 b0, u32 b1,
                                      float c0, float c1, float c2, float c3) {
    asm("mma.sync.aligned.m16n8k16.row.col.f32.bf16.bf16.f32 "
        "{%0,%1,%2,%3}, {%4,%5,%6,%7}, {%8,%9}, {%10,%11,%12,%13};"
        : "=f"(d[0]), "=f"(d[1]), "=f"(d[2]), "=f"(d[3])
        : "r"(a0), "r"(a1), "r"(a2), "r"(a3), "r"(b0), "r"(b1),
          "f"(c0), "f"(c1), "f"(c2), "f"(c3));
}
// D += A*B (in place)
__device__ __forceinline__ void mma_acc(float* d, u32 a0, u32 a1, u32 a2, u32 a3,
                                        u32 b0, u32 b1) {
    asm("mma.sync.aligned.m16n8k16.row.col.f32.bf16.bf16.f32 "
        "{%0,%1,%2,%3}, {%4,%5,%6,%7}, {%8,%9}, {%0,%1,%2,%3};"
        : "+f"(d[0]), "+f"(d[1]), "+f"(d[2]), "+f"(d[3])
        : "r"(a0), "r"(a1), "r"(a2), "r"(a3), "r"(b0), "r"(b1));
}

// Cell update, 4 cells, f32, h~=2h algebra:
//   i,f,o gates arrive prescaled by 0.5 => ti=tanh(z/2), 2*sigma(z)=ti+1.
//   c' = 0.5*((tf+1)c + (ti+1)g);  h~ = (to+1)*tanh(c') = 2h.
//   The 0.5 for h is folded into every h-consuming weight.
__device__ __forceinline__ void cell4(const float (*d)[4], float* c, float* ht) {
#pragma unroll
    for (int j = 0; j < 4; j++) {
        float ti = tanha(d[0][j]);
        float tf = tanha(d[1][j]);
        float tG = tanha(d[2][j]);
        float to = tanha(d[3][j]);
        float A  = fmaf(tf, c[j], c[j]);     // (tf+1)*c
        float Bt = fmaf(ti, tG, tG);         // (ti+1)*g
        c[j] = 0.5f * (A + Bt);
        float T = tanha(c[j]);
        ht[j] = fmaf(to, T, T);              // 2h
    }
}

// One warp = 16 sequences, 128-thread blocks, grid = B/64 (proven shape).
// Per step, per gate g (D-col block = gate, n = hidden idx):
//  L0: MMA1: D0 = [h~hi|h~lo] x [W0hi|W0hi] + C(bias, f32 exact)
//      MMA2: D0 += [h~hi|xpack] x [W0lo|Wx]   (x hi/lo + W_ih hi/lo in k8-13)
//  L1: MMA1: D1 = [h0hi|h1hi] x [B1hi] + C(bias)
//      MMA2: D1 += [h0lo|h1lo] x [B1hi];  MMA3: D1 += [h0hi|h1hi] x [B1lo]
// No f32 gate-init FFMAs, no init MOVs: bias rides in the MMA C operand and
// the x-projection rides in L0-MMA2's otherwise-idle k slots.
// Software pipeline: L0(t+1) issued before consuming L1(t).
__global__ void __launch_bounds__(128) lstm_mma7(
    const float* __restrict__ input,
    const float* __restrict__ w_ih0, const float* __restrict__ w_hh0,
    const float* __restrict__ b_ih0, const float* __restrict__ b_hh0,
    const float* __restrict__ w_ih1, const float* __restrict__ w_hh1,
    const float* __restrict__ b_ih1, const float* __restrict__ b_hh1,
    const float* __restrict__ w_mlp, const float* __restrict__ b_mlp,
    float* __restrict__ out, int B)
{
    const int T = 256;
    int lane = threadIdx.x & 31;
    int gid  = lane >> 2;          // B-frag n index / D row group
    int tg   = lane & 3;           // k/col group
    int warp = (blockIdx.x * (blockDim.x >> 5)) + (threadIdx.x >> 5);
    int wbase = warp * 16;

    int rA = wbase + gid;
    int rB = wbase + gid + 8;
    int rAc = (rA < B) ? rA : (B - 1);
    int rBc = (rB < B) ? rB : (B - 1);

    // ---- weights ----
    // s = sigmoid-gate prescale (i,f,o: 0.5; g: 1). h-consuming W get extra 0.5.
    u32 B0h[4], B0l[4], Bx[4], B1ah[4], B1bh[4], B1al[4], B1bl[4];
    float be0[4], bo0[4], be1[4], bo1[4];
#pragma unroll
    for (int g = 0; g < 4; g++) {
        int wr = g * 8 + gid;                // B n-index = gid
        float s  = (g == 2) ? 1.0f : 0.5f;
        float sh = s * 0.5f;                 // h~=2h compensation
        float a0 = sh * w_hh0[wr * 8 + tg * 2], a1 = sh * w_hh0[wr * 8 + tg * 2 + 1];
        float u0 = sh * w_ih1[wr * 8 + tg * 2], u1 = sh * w_ih1[wr * 8 + tg * 2 + 1];
        float v0 = sh * w_hh1[wr * 8 + tg * 2], v1 = sh * w_hh1[wr * 8 + tg * 2 + 1];
        B0h[g]  = bf2(rbf(a0), rbf(a1));  B0l[g]  = bf2(a0 - rbf(a0), a1 - rbf(a1));
        B1ah[g] = bf2(rbf(u0), rbf(u1));  B1al[g] = bf2(u0 - rbf(u0), u1 - rbf(u1));
        B1bh[g] = bf2(rbf(v0), rbf(v1));  B1bl[g] = bf2(v0 - rbf(v0), v1 - rbf(v1));
        // x-projection B slots (k8-13 of L0-MMA2): no h-compensation on x weights
        float wx0 = s * w_ih0[wr * 2 + 0], wx1 = s * w_ih0[wr * 2 + 1];
        float wx0h = rbf(wx0), wx1h = rbf(wx1);
        // tg0: A=(x0hi,x1hi) B=(w hi); tg1: A=(x0lo,x1lo) B=(w hi);
        // tg2: A=(x0hi,x1hi) B=(w lo); tg3: A=0
        u32 bxv;
        if (tg == 2) bxv = bf2(wx0 - wx0h, wx1 - wx1h);
        else if (tg == 3) bxv = 0u;
        else bxv = bf2(wx0h, wx1h);
        Bx[g] = bxv;
        int cE = g * 8 + tg * 2;             // D cols: hid = tg*2, tg*2+1
        be0[g] = s * (b_ih0[cE] + b_hh0[cE]);
        bo0[g] = s * (b_ih0[cE + 1] + b_hh0[cE + 1]);
        be1[g] = s * (b_ih1[cE] + b_hh1[cE]);
        bo1[g] = s * (b_ih1[cE + 1] + b_hh1[cE + 1]);
    }

    // ---- state ----
    float c0[4] = {0.f, 0.f, 0.f, 0.f};
    float c1[4] = {0.f, 0.f, 0.f, 0.f};
    float h1t[4] = {0.f, 0.f, 0.f, 0.f};
    u32 h0hL = 0, h0hH = 0, h0lL = 0, h0lH = 0;
    u32 h1hL = 0, h1hH = 0, h1lL = 0, h1lH = 0;

    const float2* xr = reinterpret_cast<const float2*>(input);

    // x pack builder: per-thread A slot for L0-MMA2 k8-15 (tg-selected hi/lo)
    auto xsel = [&](float2 x) -> u32 {
        u32 xh = bf2(x.x, x.y);
        if (tg == 3) return 0u;
        if (tg == 1) return bf2(x.x - lo_f32(xh), x.y - hi_f32(xh));
        return xh;
    };

    // ---- prologue: issue L0(0) with h~(-1)=0 ----
    float d0[4][4];
    {
        float2 xA = __ldg(&xr[(size_t)rAc * T]);
        float2 xB = __ldg(&xr[(size_t)rBc * T]);
        u32 a2x = xsel(xA), a3x = xsel(xB);
#pragma unroll
        for (int g = 0; g < 4; g++) {
            mma_c(d0[g], 0u, 0u, 0u, 0u, B0h[g], B0h[g],
                  be0[g], bo0[g], be0[g], bo0[g]);
            mma_acc(d0[g], 0u, 0u, a2x, a3x, B0l[g], Bx[g]);
        }
    }

    for (int t = 0; t < T; t++) {
        // ---- consume L0(t) -> h~0(t) ----
        float h0t[4];
        cell4(d0, c0, h0t);
        h0hL = bf2(h0t[0], h0t[1]);
        h0lL = bf2(h0t[0] - lo_f32(h0hL), h0t[1] - hi_f32(h0hL));
        h0hH = bf2(h0t[2], h0t[3]);
        h0lH = bf2(h0t[2] - lo_f32(h0hH), h0t[3] - hi_f32(h0hH));

        // ---- issue L1(t): bias in C, depth-3 chain, full hi/lo ----
        float d1[4][4];
#pragma unroll
        for (int g = 0; g < 4; g++) {
            mma_c(d1[g], h0hL, h0hH, h1hL, h1hH, B1ah[g], B1bh[g],
                  be1[g], bo1[g], be1[g], bo1[g]);
            mma_acc(d1[g], h0lL, h0lH, h1lL, h1lH, B1ah[g], B1bh[g]);
            mma_acc(d1[g], h0hL, h0hH, h1hL, h1hH, B1al[g], B1bl[g]);
        }

        // ---- issue L0(t+1): bias in C, x in k8-13 of MMA2 ----
        {
            int tn = (t < T - 1) ? (t + 1) : t;
            float2 xA = __ldg(&xr[(size_t)rAc * T + tn]);
            float2 xB = __ldg(&xr[(size_t)rBc * T + tn]);
            u32 a2x = xsel(xA), a3x = xsel(xB);
#pragma unroll
            for (int g = 0; g < 4; g++) {
                mma_c(d0[g], h0hL, h0hH, h0lL, h0lH, B0h[g], B0h[g],
                      be0[g], bo0[g], be0[g], bo0[g]);
                mma_acc(d0[g], h0hL, h0hH, a2x, a3x, B0l[g], Bx[g]);
            }
        }

        // ---- consume L1(t) -> h~1(t) ----
        cell4(d1, c1, h1t);
        h1hL = bf2(h1t[0], h1t[1]);
        h1lL = bf2(h1t[0] - lo_f32(h1hL), h1t[1] - hi_f32(h1hL));
        h1hH = bf2(h1t[2], h1t[3]);
        h1lH = bf2(h1t[2] - lo_f32(h1hH), h1t[3] - hi_f32(h1hH));
    }

    // ================= MLP head (h~=2h -> 0.5*w_mlp) =================
    int hidE = tg * 2;
    float w0e = 0.5f * w_mlp[hidE],     w0o = 0.5f * w_mlp[hidE + 1];
    float w1e = 0.5f * w_mlp[8 + hidE], w1o = 0.5f * w_mlp[8 + hidE + 1];
    float p0A = h1t[0] * w0e + h1t[1] * w0o;
    float p1A = h1t[0] * w1e + h1t[1] * w1o;
    float p0B = h1t[2] * w0e + h1t[3] * w0o;
    float p1B = h1t[2] * w1e + h1t[3] * w1o;
#pragma unroll
    for (int off = 1; off < 4; off <<= 1) {
        p0A += __shfl_xor_sync(0xffffffffu, p0A, off);
        p1A += __shfl_xor_sync(0xffffffffu, p1A, off);
        p0B += __shfl_xor_sync(0xffffffffu, p0B, off);
        p1B += __shfl_xor_sync(0xffffffffu, p1B, off);
    }
    if (tg == 0) {
        if (rA < B) {
            float2 o; o.x = p0A + b_mlp[0]; o.y = p1A + b_mlp[1];
            reinterpret_cast<float2*>(out)[rA] = o;
        }
        if (rB < B) {
            float2 o; o.x = p0B + b_mlp[0]; o.y = p1B + b_mlp[1];
            reinterpret_cast<float2*>(out)[rB] = o;
        }
    }
}

extern "C" void kernel_launch(void* const* d_in, const int* in_sizes, int n_in,
                              void* d_out, int out_size) {
    const float* input = (const float*)d_in[0];
    const float* w_ih0 = (const float*)d_in[1];
    const float* w_hh0 = (const float*)d_in[2];
    const float* b_ih0 = (const float*)d_in[3];
    const float* b_hh0 = (const float*)d_in[4];
    const float* w_ih1 = (const float*)d_in[5];
    const float* w_hh1 = (const float*)d_in[6];
    const float* b_ih1 = (const float*)d_in[7];
    const float* b_hh1 = (const float*)d_in[8];
    const float* w_mlp = (const float*)d_in[9];
    const float* b_mlp = (const float*)d_in[10];

    const int T = 256, IN = 2;
    int B = in_sizes[0] / (T * IN);

    int grid = (B + 63) / 64;      // 16 seqs/warp, 4 warps/block
    lstm_mma7<<<grid, 128>>>(input, w_ih0, w_hh0, b_ih0, b_hh0,
                             w_ih1, w_hh1, b_ih1, b_hh1,
                             w_mlp, b_mlp, (float*)d_out, B);
}

// round 13
// speedup vs baseline: 1.2624x; 1.1003x over previous
#include <cuda_runtime.h>
#include <cuda_bf16.h>
#include <cstdint>

typedef uint32_t u32;

// ---- bf16 helpers ----
__device__ __forceinline__ u32 bf2(float lo, float hi) {   // lo -> low 16 bits
    u32 r; asm("cvt.rn.bf16x2.f32 %0, %1, %2;" : "=r"(r) : "f"(hi), "f"(lo)); return r;
}
__device__ __forceinline__ float lo_f32(u32 p) { return __uint_as_float(p << 16); }
__device__ __forceinline__ float hi_f32(u32 p) { return __uint_as_float(p & 0xFFFF0000u); }
__device__ __forceinline__ float rbf(float v) {
    return __bfloat162float(__float2bfloat16(v));
}

// ---- f32 tanh (MUFU) ----
__device__ __forceinline__ float tanha(float x) {
    float r; asm("tanh.approx.f32 %0, %1;" : "=f"(r) : "f"(x)); return r;
}

// D += A * B  (m16n8k16, bf16 in, f32 accum), accumulate in place
__device__ __forceinline__ void mma16816(float* d, u32 a0, u32 a1, u32 a2, u32 a3,
                                         u32 b0, u32 b1) {
    asm("mma.sync.aligned.m16n8k16.row.col.f32.bf16.bf16.f32 "
        "{%0,%1,%2,%3}, {%4,%5,%6,%7}, {%8,%9}, {%0,%1,%2,%3};"
        : "+f"(d[0]), "+f"(d[1]), "+f"(d[2]), "+f"(d[3])
        : "r"(a0), "r"(a1), "r"(a2), "r"(a3), "r"(b0), "r"(b1));
}

// Cell update, 4 cells, f32 MUFU, h~=2h algebra:
//   i,f,o prescaled by 0.5 => ti=tanh(z/2); 2*sigma(z)=ti+1.
//   c' = 0.5*((tf+1)c + (ti+1)g);  h~ = (to+1)*tanh(c') = 2h.
//   The extra 0.5 for h~ is folded into every h-consuming weight.
__device__ __forceinline__ void cell4(const float (*d)[4], float* c, float* ht) {
#pragma unroll
    for (int j = 0; j < 4; j++) {
        float ti = tanha(d[0][j]);
        float tf = tanha(d[1][j]);
        float tG = tanha(d[2][j]);
        float to = tanha(d[3][j]);
        float A  = fmaf(tf, c[j], c[j]);     // (tf+1)*c = 2*f*c
        float Bt = fmaf(ti, tG, tG);         // (ti+1)*g = 2*i*g
        c[j] = 0.5f * (A + Bt);
        float T = tanha(c[j]);
        ht[j] = fmaf(to, T, T);              // 2h
    }
}

// One warp = 16 sequences, 128-thread blocks, grid = B/64 (proven shape).
// DEEP software pipeline (layer-0 runs one step ahead of layer-1):
//   iter t:  A: issue L1(t)   [h0(t), h1(t-1)]  d1 depth-1 + e1 depth-2
//            B: consume L0(t+1) -> h0(t+1)      (cell4 covers A's MMA latency)
//            C: issue L0(t+2)  [h0(t+1)]        d0: FFMA init + depth-2 chain
//            D: consume L1(t) -> h1(t)          (gate = d1 + e1)
// Full hi/lo weight precision on both layers. x-proj + bias exact f32 FFMA.
__global__ void __launch_bounds__(128) lstm_mma8(
    const float* __restrict__ input,
    const float* __restrict__ w_ih0, const float* __restrict__ w_hh0,
    const float* __restrict__ b_ih0, const float* __restrict__ b_hh0,
    const float* __restrict__ w_ih1, const float* __restrict__ w_hh1,
    const float* __restrict__ b_ih1, const float* __restrict__ b_hh1,
    const float* __restrict__ w_mlp, const float* __restrict__ b_mlp,
    float* __restrict__ out, int B)
{
    const int T = 256;
    int lane = threadIdx.x & 31;
    int gid  = lane >> 2;          // B-frag n index / D row group
    int tg   = lane & 3;           // k/col group
    int warp = (blockIdx.x * (blockDim.x >> 5)) + (threadIdx.x >> 5);
    int wbase = warp * 16;

    int rA = wbase + gid;
    int rB = wbase + gid + 8;
    int rAc = (rA < B) ? rA : (B - 1);
    int rBc = (rB < B) ? rB : (B - 1);

    // ---- weights: bf16 hi+lo B frags (extra 0.5 for h~=2h), f32 x-w, biases ----
    u32 B0h[4], B0l[4], B1ah[4], B1bh[4], B1al[4], B1bl[4];
    float wi00[4], wi01[4], wi10[4], wi11[4];
    float be0[4], bo0[4], be1[4], bo1[4];
#pragma unroll
    for (int g = 0; g < 4; g++) {
        int wr = g * 8 + gid;
        float s  = (g == 2) ? 1.0f : 0.5f;   // sigmoid prescale
        float sh = s * 0.5f;                 // + h~=2h compensation
        float a0 = sh * w_hh0[wr * 8 + tg * 2], a1 = sh * w_hh0[wr * 8 + tg * 2 + 1];
        float u0 = sh * w_ih1[wr * 8 + tg * 2], u1 = sh * w_ih1[wr * 8 + tg * 2 + 1];
        float v0 = sh * w_hh1[wr * 8 + tg * 2], v1 = sh * w_hh1[wr * 8 + tg * 2 + 1];
        B0h[g]  = bf2(rbf(a0), rbf(a1));  B0l[g]  = bf2(a0 - rbf(a0), a1 - rbf(a1));
        B1ah[g] = bf2(rbf(u0), rbf(u1));  B1al[g] = bf2(u0 - rbf(u0), u1 - rbf(u1));
        B1bh[g] = bf2(rbf(v0), rbf(v1));  B1bl[g] = bf2(v0 - rbf(v0), v1 - rbf(v1));
        int cE = g * 8 + tg * 2;             // D cols: hid = tg*2, tg*2+1
        wi00[g] = s * w_ih0[cE * 2];         wi01[g] = s * w_ih0[cE * 2 + 1];
        wi10[g] = s * w_ih0[(cE + 1) * 2];   wi11[g] = s * w_ih0[(cE + 1) * 2 + 1];
        be0[g] = s * (b_ih0[cE] + b_hh0[cE]);
        bo0[g] = s * (b_ih0[cE + 1] + b_hh0[cE + 1]);
        be1[g] = s * (b_ih1[cE] + b_hh1[cE]);
        bo1[g] = s * (b_ih1[cE + 1] + b_hh1[cE + 1]);
    }

    // ---- state ----
    float c0[4] = {0.f, 0.f, 0.f, 0.f};
    float c1[4] = {0.f, 0.f, 0.f, 0.f};
    float h1t[4] = {0.f, 0.f, 0.f, 0.f};
    u32 h0hL = 0, h0hH = 0, h0lL = 0, h0lH = 0;
    u32 h1hL = 0, h1hH = 0, h1lL = 0, h1lH = 0;

    const float2* xr = reinterpret_cast<const float2*>(input);

    float d0[4][4];
    // ---- prologue ----
    {
        // L0(0): gates = bias + Wih*x(0)  (h0(-1)=0, pure FFMA) -> h0(0)
        float2 xA = __ldg(&xr[(size_t)rAc * T]);
        float2 xB = __ldg(&xr[(size_t)rBc * T]);
        float g0[4][4];
#pragma unroll
        for (int g = 0; g < 4; g++) {
            g0[g][0] = fmaf(wi01[g], xA.y, fmaf(wi00[g], xA.x, be0[g]));
            g0[g][1] = fmaf(wi11[g], xA.y, fmaf(wi10[g], xA.x, bo0[g]));
            g0[g][2] = fmaf(wi01[g], xB.y, fmaf(wi00[g], xB.x, be0[g]));
            g0[g][3] = fmaf(wi11[g], xB.y, fmaf(wi10[g], xB.x, bo0[g]));
        }
        float h0t[4];
        cell4(g0, c0, h0t);
        h0hL = bf2(h0t[0], h0t[1]);
        h0lL = bf2(h0t[0] - lo_f32(h0hL), h0t[1] - hi_f32(h0hL));
        h0hH = bf2(h0t[2], h0t[3]);
        h0lH = bf2(h0t[2] - lo_f32(h0hH), h0t[3] - hi_f32(h0hH));

        // issue L0(1)
        xA = __ldg(&xr[(size_t)rAc * T + 1]);
        xB = __ldg(&xr[(size_t)rBc * T + 1]);
#pragma unroll
        for (int g = 0; g < 4; g++) {
            d0[g][0] = fmaf(wi01[g], xA.y, fmaf(wi00[g], xA.x, be0[g]));
            d0[g][1] = fmaf(wi11[g], xA.y, fmaf(wi10[g], xA.x, bo0[g]));
            d0[g][2] = fmaf(wi01[g], xB.y, fmaf(wi00[g], xB.x, be0[g]));
            d0[g][3] = fmaf(wi11[g], xB.y, fmaf(wi10[g], xB.x, bo0[g]));
            mma16816(d0[g], h0hL, h0hH, h0lL, h0lH, B0h[g], B0h[g]);
            mma16816(d0[g], h0hL, h0hH, 0u, 0u, B0l[g], B0l[g]);
        }
    }

    for (int t = 0; t < T; t++) {
        // ---- A: issue L1(t) using h0(t), h1(t-1) ----
        float d1[4][4], e1[4][4];
#pragma unroll
        for (int g = 0; g < 4; g++) {
            d1[g][0] = be1[g]; d1[g][1] = bo1[g];
            d1[g][2] = be1[g]; d1[g][3] = bo1[g];
            e1[g][0] = 0.f; e1[g][1] = 0.f; e1[g][2] = 0.f; e1[g][3] = 0.f;
            mma16816(d1[g], h0hL, h0hH, h1hL, h1hH, B1ah[g], B1bh[g]);  // depth-1
            mma16816(e1[g], h0lL, h0lH, h1lL, h1lH, B1ah[g], B1bh[g]);  // depth-2
            mma16816(e1[g], h0hL, h0hH, h1hL, h1hH, B1al[g], B1bl[g]);  //   chain
        }

        // ---- B: consume L0(t+1) -> h0(t+1)  (MUFU cover for A's MMAs) ----
        float h0t[4];
        cell4(d0, c0, h0t);
        h0hL = bf2(h0t[0], h0t[1]);
        h0lL = bf2(h0t[0] - lo_f32(h0hL), h0t[1] - hi_f32(h0hL));
        h0hH = bf2(h0t[2], h0t[3]);
        h0lH = bf2(h0t[2] - lo_f32(h0hH), h0t[3] - hi_f32(h0hH));

        // ---- C: issue L0(t+2) using h0(t+1) ----
        {
            int tn = (t + 2 < T) ? (t + 2) : (T - 1);
            float2 xA = __ldg(&xr[(size_t)rAc * T + tn]);
            float2 xB = __ldg(&xr[(size_t)rBc * T + tn]);
#pragma unroll
            for (int g = 0; g < 4; g++) {
                d0[g][0] = fmaf(wi01[g], xA.y, fmaf(wi00[g], xA.x, be0[g]));
                d0[g][1] = fmaf(wi11[g], xA.y, fmaf(wi10[g], xA.x, bo0[g]));
                d0[g][2] = fmaf(wi01[g], xB.y, fmaf(wi00[g], xB.x, be0[g]));
                d0[g][3] = fmaf(wi11[g], xB.y, fmaf(wi10[g], xB.x, bo0[g]));
                mma16816(d0[g], h0hL, h0hH, h0lL, h0lH, B0h[g], B0h[g]);
                mma16816(d0[g], h0hL, h0hH, 0u, 0u, B0l[g], B0l[g]);
            }
        }

        // ---- D: consume L1(t) -> h1(t) ----
        float gs[4][4];
#pragma unroll
        for (int g = 0; g < 4; g++) {
#pragma unroll
            for (int j = 0; j < 4; j++) gs[g][j] = d1[g][j] + e1[g][j];
        }
        cell4(gs, c1, h1t);
        h1hL = bf2(h1t[0], h1t[1]);
        h1lL = bf2(h1t[0] - lo_f32(h1hL), h1t[1] - hi_f32(h1hL));
        h1hH = bf2(h1t[2], h1t[3]);
        h1lH = bf2(h1t[2] - lo_f32(h1hH), h1t[3] - hi_f32(h1hH));
    }

    // ================= MLP head (h~=2h -> 0.5*w_mlp) =================
    int hidE = tg * 2;
    float w0e = 0.5f * w_mlp[hidE],     w0o = 0.5f * w_mlp[hidE + 1];
    float w1e = 0.5f * w_mlp[8 + hidE], w1o = 0.5f * w_mlp[8 + hidE + 1];
    float p0A = h1t[0] * w0e + h1t[1] * w0o;
    float p1A = h1t[0] * w1e + h1t[1] * w1o;
    float p0B = h1t[2] * w0e + h1t[3] * w0o;
    float p1B = h1t[2] * w1e + h1t[3] * w1o;
#pragma unroll
    for (int off = 1; off < 4; off <<= 1) {
        p0A += __shfl_xor_sync(0xffffffffu, p0A, off);
        p1A += __shfl_xor_sync(0xffffffffu, p1A, off);
        p0B += __shfl_xor_sync(0xffffffffu, p0B, off);
        p1B += __shfl_xor_sync(0xffffffffu, p1B, off);
    }
    if (tg == 0) {
        if (rA < B) {
            float2 o; o.x = p0A + b_mlp[0]; o.y = p1A + b_mlp[1];
            reinterpret_cast<float2*>(out)[rA] = o;
        }
        if (rB < B) {
            float2 o; o.x = p0B + b_mlp[0]; o.y = p1B + b_mlp[1];
            reinterpret_cast<float2*>(out)[rB] = o;
        }
    }
}

extern "C" void kernel_launch(void* const* d_in, const int* in_sizes, int n_in,
                              void* d_out, int out_size) {
    const float* input = (const float*)d_in[0];
    const float* w_ih0 = (const float*)d_in[1];
    const float* w_hh0 = (const float*)d_in[2];
    const float* b_ih0 = (const float*)d_in[3];
    const float* b_hh0 = (const float*)d_in[4];
    const float* w_ih1 = (const float*)d_in[5];
    const float* w_hh1 = (const float*)d_in[6];
    const float* b_ih1 = (const float*)d_in[7];
    const float* b_hh1 = (const float*)d_in[8];
    const float* w_mlp = (const float*)d_in[9];
    const float* b_mlp = (const float*)d_in[10];

    const int T = 256, IN = 2;
    int B = in_sizes[0] / (T * IN);

    int grid = (B + 63) / 64;      // 16 seqs/warp, 4 warps/block
    lstm_mma8<<<grid, 128>>>(input, w_ih0, w_hh0, b_ih0, b_hh0,
                             w_ih1, w_hh1, b_ih1, b_hh1,
                             w_mlp, b_mlp, (float*)d_out, B);
}

// round 14
// speedup vs baseline: 1.3715x; 1.0865x over previous
#include <cuda_runtime.h>
#include <cuda_fp16.h>
#include <cstdint>

typedef uint32_t u32;

// ---- f16x2 helpers ----
__device__ __forceinline__ u32 pk16(float lo, float hi) {  // lo -> low half
    u32 r; asm("cvt.rn.f16x2.f32 %0, %1, %2;" : "=r"(r) : "f"(hi), "f"(lo)); return r;
}
__device__ __forceinline__ void up16(u32 p, float& lo, float& hi) {
    asm("{ .reg .b16 l, h; mov.b32 {l, h}, %2; cvt.f32.f16 %0, l; cvt.f32.f16 %1, h; }"
        : "=f"(lo), "=f"(hi) : "r"(p));
}
__device__ __forceinline__ u32 th2(u32 x) {                // 2x tanh, 1 MUFU
    u32 r; asm("tanh.approx.f16x2 %0, %1;" : "=r"(r) : "r"(x)); return r;
}
__device__ __forceinline__ u32 sg2(u32 t) {                // t*0.5+0.5 packed
    u32 r; asm("fma.rn.f16x2 %0, %1, %2, %2;" : "=r"(r) : "r"(t), "r"(0x38003800u)); return r;
}
__device__ __forceinline__ u32 hmul2(u32 a, u32 b) {
    u32 r; asm("mul.rn.f16x2 %0, %1, %2;" : "=r"(r) : "r"(a), "r"(b)); return r;
}
// f32 value rounded to f16, returned as f32
__device__ __forceinline__ float rh(float v) {
    return __half2float(__float2half_rn(v));
}
// f32 tanh (MUFU) for epilogue-precision path
__device__ __forceinline__ float tanha(float x) {
    float r; asm("tanh.approx.f32 %0, %1;" : "=f"(r) : "f"(x)); return r;
}
__device__ __forceinline__ float sigp(float hz) { return fmaf(tanha(hz), 0.5f, 0.5f); }

// m16n8k16 all-f16 MMA: D (2x f16x2) = A*B + C
__device__ __forceinline__ void mma_h(u32& d0, u32& d1,
                                      u32 a0, u32 a1, u32 a2, u32 a3,
                                      u32 b0, u32 b1, u32 c0, u32 c1) {
    asm("mma.sync.aligned.m16n8k16.row.col.f16.f16.f16.f16 "
        "{%0,%1}, {%2,%3,%4,%5}, {%6,%7}, {%8,%9};"
        : "=r"(d0), "=r"(d1)
        : "r"(a0), "r"(a1), "r"(a2), "r"(a3), "r"(b0), "r"(b1), "r"(c0), "r"(c1));
}
// D += A*B (chained)
__device__ __forceinline__ void mma_h_acc(u32& d0, u32& d1,
                                          u32 a0, u32 a1, u32 a2, u32 a3,
                                          u32 b0, u32 b1) {
    asm("mma.sync.aligned.m16n8k16.row.col.f16.f16.f16.f16 "
        "{%0,%1}, {%2,%3,%4,%5}, {%6,%7}, {%0,%1};"
        : "+r"(d0), "+r"(d1)
        : "r"(a0), "r"(a1), "r"(a2), "r"(a3), "r"(b0), "r"(b1));
}

// All-f16x2 LSTM cell, 4 cells (2 f16x2 lanes): gate preacts arrive as f16x2
// MMA D regs (i,f,o prescaled by 0.5 => sigmoid = tanh2*0.5+0.5). c is f32.
// Output h packs are f16x2 in EXACTLY the next MMA's A-fragment layout.
__device__ __forceinline__ void cell_h(u32 dI0, u32 dI1, u32 dF0, u32 dF1,
                                       u32 dG0, u32 dG1, u32 dO0, u32 dO1,
                                       float* c, u32& hp0, u32& hp1) {
    u32 iv0 = sg2(th2(dI0)), iv1 = sg2(th2(dI1));
    u32 fv0 = sg2(th2(dF0)), fv1 = sg2(th2(dF1));
    u32 gv0 = th2(dG0),      gv1 = th2(dG1);
    u32 ov0 = sg2(th2(dO0)), ov1 = sg2(th2(dO1));
    u32 ig0 = hmul2(iv0, gv0), ig1 = hmul2(iv1, gv1);
    float ia, ib, ic2, id2, fa, fb, fc2, fd2;
    up16(ig0, ia, ib);  up16(ig1, ic2, id2);
    up16(fv0, fa, fb);  up16(fv1, fc2, fd2);
    c[0] = fmaf(fa,  c[0], ia);
    c[1] = fmaf(fb,  c[1], ib);
    c[2] = fmaf(fc2, c[2], ic2);
    c[3] = fmaf(fd2, c[3], id2);
    u32 tc0 = th2(pk16(c[0], c[1]));
    u32 tc1 = th2(pk16(c[2], c[3]));
    hp0 = hmul2(ov0, tc0);
    hp1 = hmul2(ov1, tc1);
}

// One warp = 16 sequences (proven shape), all-f16 HMMA datapath.
// Per step, per gate g:
//   L0: D0 = [h0 | x,0..] x [W0hi | Wxhi] + C(bias f16)  then += x [W0lo | Wxlo]
//   L1: D1 = [h0 | h1]    x [W1hi]        + C(bias f16)  then += x [W1lo]
// Weights f16 hi+lo (systematic error ~0); h/x single f16 (random, damped).
// D/A f16x2 layouts coincide -> h recirculates with ZERO conversions.
// Deep pipeline (R13): L0 runs one step ahead of L1.
__global__ void __launch_bounds__(128) lstm_hmma(
    const float* __restrict__ input,
    const float* __restrict__ w_ih0, const float* __restrict__ w_hh0,
    const float* __restrict__ b_ih0, const float* __restrict__ b_hh0,
    const float* __restrict__ w_ih1, const float* __restrict__ w_hh1,
    const float* __restrict__ b_ih1, const float* __restrict__ b_hh1,
    const float* __restrict__ w_mlp, const float* __restrict__ b_mlp,
    float* __restrict__ out, int B)
{
    const int T = 256;
    int lane = threadIdx.x & 31;
    int gid  = lane >> 2;          // B-frag n index / D-A row group
    int tg   = lane & 3;           // k/col pair group
    int warp = (blockIdx.x * (blockDim.x >> 5)) + (threadIdx.x >> 5);
    int wbase = warp * 16;

    int rA = wbase + gid;
    int rB = wbase + gid + 8;
    int rAc = (rA < B) ? rA : (B - 1);
    int rBc = (rB < B) ? rB : (B - 1);

    // ---- weights: f16 hi+lo fragments; i,f,o rows prescaled by 0.5 ----
    // B b0 = (col gid, k=2tg,2tg+1); b1 = (col gid, k=8+2tg,9+2tg)
    u32 B0h0[4], B0h1[4], B0l0[4], B0l1[4];
    u32 B1h0[4], B1h1[4], B1l0[4], B1l1[4];
    u32 cb0[4], cb1[4];
#pragma unroll
    for (int g = 0; g < 4; g++) {
        int wr = g * 8 + gid;
        float s = (g == 2) ? 1.0f : 0.5f;
        // L0 k0-7: w_hh0
        float w0 = s * w_hh0[wr * 8 + 2 * tg], w1 = s * w_hh0[wr * 8 + 2 * tg + 1];
        float w0h = rh(w0), w1h = rh(w1);
        B0h0[g] = pk16(w0h, w1h);
        B0l0[g] = pk16(w0 - w0h, w1 - w1h);
        // L0 k8-15: k8,9 = w_ih0 (tg==0 only), rest 0
        float v0 = 0.f, v1 = 0.f;
        if (tg == 0) { v0 = s * w_ih0[wr * 2]; v1 = s * w_ih0[wr * 2 + 1]; }
        float v0h = rh(v0), v1h = rh(v1);
        B0h1[g] = pk16(v0h, v1h);
        B0l1[g] = pk16(v0 - v0h, v1 - v1h);
        // L1 k0-7: w_ih1 (vs h0), k8-15: w_hh1 (vs h1)
        float u0 = s * w_ih1[wr * 8 + 2 * tg], u1 = s * w_ih1[wr * 8 + 2 * tg + 1];
        float u0h = rh(u0), u1h = rh(u1);
        B1h0[g] = pk16(u0h, u1h);
        B1l0[g] = pk16(u0 - u0h, u1 - u1h);
        float q0 = s * w_hh1[wr * 8 + 2 * tg], q1 = s * w_hh1[wr * 8 + 2 * tg + 1];
        float q0h = rh(q0), q1h = rh(q1);
        B1h1[g] = pk16(q0h, q1h);
        B1l1[g] = pk16(q0 - q0h, q1 - q1h);
        // biases as f16x2 C operand (D cols 2tg, 2tg+1; same for both row groups)
        int cE = g * 8 + 2 * tg;
        cb0[g] = pk16(s * (b_ih0[cE] + b_hh0[cE]), s * (b_ih0[cE + 1] + b_hh0[cE + 1]));
        cb1[g] = pk16(s * (b_ih1[cE] + b_hh1[cE]), s * (b_ih1[cE + 1] + b_hh1[cE + 1]));
    }

    // ---- state ----
    float c0[4] = {0.f, 0.f, 0.f, 0.f};
    float c1[4] = {0.f, 0.f, 0.f, 0.f};
    u32 h0p0 = 0, h0p1 = 0, h1p0 = 0, h1p1 = 0;
    u32 d0a[4], d0b[4], d1a[4], d1b[4];

    const float2* xr = reinterpret_cast<const float2*>(input);
    // x A-slot: only tg==0 carries (k8,k9); others zero
    auto xsel = [&](float2 x) -> u32 { return (tg == 0) ? pk16(x.x, x.y) : 0u; };

    // ---- prologue ----
    {
        // L0(0) with h0(-1)=0
        float2 xA = __ldg(&xr[(size_t)rAc * T]);
        float2 xB = __ldg(&xr[(size_t)rBc * T]);
        u32 xa2 = xsel(xA), xa3 = xsel(xB);
#pragma unroll
        for (int g = 0; g < 4; g++) {
            mma_h(d0a[g], d0b[g], 0u, 0u, xa2, xa3, B0h0[g], B0h1[g], cb0[g], cb0[g]);
            mma_h_acc(d0a[g], d0b[g], 0u, 0u, xa2, xa3, B0l0[g], B0l1[g]);
        }
        // consume -> h0(0)
        cell_h(d0a[0], d0b[0], d0a[1], d0b[1], d0a[2], d0b[2], d0a[3], d0b[3],
               c0, h0p0, h0p1);
        // issue L0(1)
        xA = __ldg(&xr[(size_t)rAc * T + 1]);
        xB = __ldg(&xr[(size_t)rBc * T + 1]);
        xa2 = xsel(xA); xa3 = xsel(xB);
#pragma unroll
        for (int g = 0; g < 4; g++) {
            mma_h(d0a[g], d0b[g], h0p0, h0p1, xa2, xa3, B0h0[g], B0h1[g], cb0[g], cb0[g]);
            mma_h_acc(d0a[g], d0b[g], h0p0, h0p1, xa2, xa3, B0l0[g], B0l1[g]);
        }
    }

    for (int t = 0; t < T; t++) {
        // ---- A: issue L1(t) using h0(t), h1(t-1) ----
#pragma unroll
        for (int g = 0; g < 4; g++) {
            mma_h(d1a[g], d1b[g], h0p0, h0p1, h1p0, h1p1, B1h0[g], B1h1[g], cb1[g], cb1[g]);
            mma_h_acc(d1a[g], d1b[g], h0p0, h0p1, h1p0, h1p1, B1l0[g], B1l1[g]);
        }

        // ---- B: consume L0(t+1) -> h0(t+1)  (covers A's MMA latency) ----
        cell_h(d0a[0], d0b[0], d0a[1], d0b[1], d0a[2], d0b[2], d0a[3], d0b[3],
               c0, h0p0, h0p1);

        // ---- C: issue L0(t+2) using h0(t+1) ----
        {
            int tn = (t + 2 < T) ? (t + 2) : (T - 1);
            float2 xA = __ldg(&xr[(size_t)rAc * T + tn]);
            float2 xB = __ldg(&xr[(size_t)rBc * T + tn]);
            u32 xa2 = xsel(xA), xa3 = xsel(xB);
#pragma unroll
            for (int g = 0; g < 4; g++) {
                mma_h(d0a[g], d0b[g], h0p0, h0p1, xa2, xa3, B0h0[g], B0h1[g], cb0[g], cb0[g]);
                mma_h_acc(d0a[g], d0b[g], h0p0, h0p1, xa2, xa3, B0l0[g], B0l1[g]);
            }
        }

        // ---- D: consume L1(t) -> h1(t) ----
        if (t < T - 1) {
            cell_h(d1a[0], d1b[0], d1a[1], d1b[1], d1a[2], d1b[2], d1a[3], d1b[3],
                   c1, h1p0, h1p1);
        } else {
            // final step: update c1 only; h1(T-1) recomputed in f32 below
            u32 iv0 = sg2(th2(d1a[0])), iv1 = sg2(th2(d1b[0]));
            u32 fv0 = sg2(th2(d1a[1])), fv1 = sg2(th2(d1b[1]));
            u32 gv0 = th2(d1a[2]),      gv1 = th2(d1b[2]);
            u32 ig0 = hmul2(iv0, gv0),  ig1 = hmul2(iv1, gv1);
            float ia, ib, ic2, id2, fa, fb, fc2, fd2;
            up16(ig0, ia, ib);  up16(ig1, ic2, id2);
            up16(fv0, fa, fb);  up16(fv1, fc2, fd2);
            c1[0] = fmaf(fa,  c1[0], ia);
            c1[1] = fmaf(fb,  c1[1], ib);
            c1[2] = fmaf(fc2, c1[2], ic2);
            c1[3] = fmaf(fd2, c1[3], id2);
        }
    }

    // ---- final h1 in f32 (o-gate preacts from last d1, c1 is f32) ----
    float h1f[4];
    {
        float o0, o1, o2, o3;
        up16(d1a[3], o0, o1);
        up16(d1b[3], o2, o3);
        h1f[0] = sigp(o0) * tanha(c1[0]);
        h1f[1] = sigp(o1) * tanha(c1[1]);
        h1f[2] = sigp(o2) * tanha(c1[2]);
        h1f[3] = sigp(o3) * tanha(c1[3]);
    }

    // ================= MLP head =================
    int hidE = tg * 2;
    float w0e = w_mlp[hidE],     w0o = w_mlp[hidE + 1];
    float w1e = w_mlp[8 + hidE], w1o = w_mlp[8 + hidE + 1];
    float p0A = h1f[0] * w0e + h1f[1] * w0o;
    float p1A = h1f[0] * w1e + h1f[1] * w1o;
    float p0B = h1f[2] * w0e + h1f[3] * w0o;
    float p1B = h1f[2] * w1e + h1f[3] * w1o;
#pragma unroll
    for (int off = 1; off < 4; off <<= 1) {
        p0A += __shfl_xor_sync(0xffffffffu, p0A, off);
        p1A += __shfl_xor_sync(0xffffffffu, p1A, off);
        p0B += __shfl_xor_sync(0xffffffffu, p0B, off);
        p1B += __shfl_xor_sync(0xffffffffu, p1B, off);
    }
    if (tg == 0) {
        if (rA < B) {
            float2 o; o.x = p0A + b_mlp[0]; o.y = p1A + b_mlp[1];
            reinterpret_cast<float2*>(out)[rA] = o;
        }
        if (rB < B) {
            float2 o; o.x = p0B + b_mlp[0]; o.y = p1B + b_mlp[1];
            reinterpret_cast<float2*>(out)[rB] = o;
        }
    }
}

extern "C" void kernel_launch(void* const* d_in, const int* in_sizes, int n_in,
                              void* d_out, int out_size) {
    const float* input = (const float*)d_in[0];
    const float* w_ih0 = (const float*)d_in[1];
    const float* w_hh0 = (const float*)d_in[2];
    const float* b_ih0 = (const float*)d_in[3];
    const float* b_hh0 = (const float*)d_in[4];
    const float* w_ih1 = (const float*)d_in[5];
    const float* w_hh1 = (const float*)d_in[6];
    const float* b_ih1 = (const float*)d_in[7];
    const float* b_hh1 = (const float*)d_in[8];
    const float* w_mlp = (const float*)d_in[9];
    const float* b_mlp = (const float*)d_in[10];

    const int T = 256, IN = 2;
    int B = in_sizes[0] / (T * IN);

    int grid = (B + 63) / 64;      // 16 seqs/warp, 4 warps/block
    lstm_hmma<<<grid, 128>>>(input, w_ih0, w_hh0, b_ih0, b_hh0,
                             w_ih1, w_hh1, b_ih1, b_hh1,
                             w_mlp, b_mlp, (float*)d_out, B);
}